// round 1
// baseline (speedup 1.0000x reference)
#include <cuda_runtime.h>
#include <cstdint>

#define BB 8
#define NN 4096
#define MM 4096
#define KK 64
#define TILE 128
#define PAD 68           // 64 + 4 floats; row stride 272B, float4-aligned

// -------- scratch (allocation-free: __device__ globals) --------
__device__ float    g_x2[BB * NN];
__device__ float    g_y2[BB * MM];
__device__ unsigned g_rmin[BB * NN];   // min over m of sq, per (b,n)  -> dist1
__device__ unsigned g_cmin[BB * MM];   // min over n of sq, per (b,m)  -> dist0

// -------- init minima to +inf --------
__global__ void chamfer_init_kernel() {
    int t = blockIdx.x * blockDim.x + threadIdx.x;
    if (t < BB * NN) g_rmin[t] = 0x7f800000u;
    if (t < BB * MM) g_cmin[t] = 0x7f800000u;
}

// -------- squared norms of every row --------
__global__ void chamfer_sqnorm_kernel(const float* __restrict__ X,
                                      const float* __restrict__ Y) {
    int t = blockIdx.x * blockDim.x + threadIdx.x;
    const float* src;
    float* dst;
    int idx;
    if (t < BB * NN) { src = X; dst = g_x2; idx = t; }
    else             { src = Y; dst = g_y2; idx = t - BB * NN; }
    const float4* p = reinterpret_cast<const float4*>(src + (size_t)idx * KK);
    float s = 0.f;
#pragma unroll
    for (int i = 0; i < KK / 4; ++i) {
        float4 v = p[i];
        s += v.x * v.x + v.y * v.y + v.z * v.z + v.w * v.w;
    }
    dst[idx] = s;
}

// -------- main fused tile kernel --------
// Grid: (MM/TILE, NN/TILE, BB). 256 threads as 16x16; each thread owns an
// 8x8 sub-tile: rows r_i = ty*8+i (blocked), cols c_j = j*16+tx (strided).
__global__ __launch_bounds__(256, 2)
void chamfer_tile_kernel(const float* __restrict__ X,
                         const float* __restrict__ Y) {
    extern __shared__ float smem[];
    float* As = smem;               // [TILE][PAD]
    float* Bs = smem + TILE * PAD;  // [TILE][PAD]

    const int b  = blockIdx.z;
    const int n0 = blockIdx.y * TILE;
    const int m0 = blockIdx.x * TILE;
    const int tid = threadIdx.x;
    const int tx = tid & 15;
    const int ty = tid >> 4;

    const float* Xb = X + ((size_t)b * NN + n0) * KK;
    const float* Yb = Y + ((size_t)b * MM + m0) * KK;

    // Fill both tiles: 128 rows x 16 float4 each, 2048 float4 per tile.
#pragma unroll
    for (int it = 0; it < 8; ++it) {
        int idx = it * 256 + tid;
        int r  = idx >> 4;
        int kq = idx & 15;
        float4 va = *reinterpret_cast<const float4*>(Xb + r * KK + kq * 4);
        float4 vb = *reinterpret_cast<const float4*>(Yb + r * KK + kq * 4);
        *reinterpret_cast<float4*>(As + r * PAD + kq * 4) = va;
        *reinterpret_cast<float4*>(Bs + r * PAD + kq * 4) = vb;
    }
    __syncthreads();

    float acc[8][8];
#pragma unroll
    for (int i = 0; i < 8; ++i)
#pragma unroll
        for (int j = 0; j < 8; ++j) acc[i][j] = 0.f;

#pragma unroll
    for (int k4 = 0; k4 < KK / 4; ++k4) {
        float4 a4[8];
#pragma unroll
        for (int i = 0; i < 8; ++i)
            a4[i] = *reinterpret_cast<const float4*>(As + (ty * 8 + i) * PAD + k4 * 4);
#pragma unroll
        for (int j = 0; j < 8; ++j) {
            float4 bv = *reinterpret_cast<const float4*>(Bs + (j * 16 + tx) * PAD + k4 * 4);
#pragma unroll
            for (int i = 0; i < 8; ++i) {
                acc[i][j] += a4[i].x * bv.x;
                acc[i][j] += a4[i].y * bv.y;
                acc[i][j] += a4[i].z * bv.z;
                acc[i][j] += a4[i].w * bv.w;
            }
        }
    }

    // Epilogue: sq = x2 + y2 - 2*dot, clamp >= 0, track mins.
    float x2v[8], y2v[8];
#pragma unroll
    for (int i = 0; i < 8; ++i) x2v[i] = g_x2[b * NN + n0 + ty * 8 + i];
#pragma unroll
    for (int j = 0; j < 8; ++j) y2v[j] = g_y2[b * MM + m0 + j * 16 + tx];

    float rmin[8], cmin[8];
#pragma unroll
    for (int i = 0; i < 8; ++i) rmin[i] = __int_as_float(0x7f800000);
#pragma unroll
    for (int j = 0; j < 8; ++j) cmin[j] = __int_as_float(0x7f800000);

#pragma unroll
    for (int i = 0; i < 8; ++i) {
#pragma unroll
        for (int j = 0; j < 8; ++j) {
            float sq = fmaxf(x2v[i] + y2v[j] - 2.f * acc[i][j], 0.f);
            rmin[i] = fminf(rmin[i], sq);
            cmin[j] = fminf(cmin[j], sq);
        }
    }

    // Shared reduction then one global atomicMin per row/col of the tile.
    __syncthreads();  // done reading As/Bs
    unsigned* s_rmin = reinterpret_cast<unsigned*>(smem);
    unsigned* s_cmin = s_rmin + TILE;
    if (tid < TILE) { s_rmin[tid] = 0x7f800000u; s_cmin[tid] = 0x7f800000u; }
    __syncthreads();
#pragma unroll
    for (int i = 0; i < 8; ++i)
        atomicMin(&s_rmin[ty * 8 + i], __float_as_uint(rmin[i]));
#pragma unroll
    for (int j = 0; j < 8; ++j)
        atomicMin(&s_cmin[j * 16 + tx], __float_as_uint(cmin[j]));
    __syncthreads();

    if (tid < TILE) {
        atomicMin(&g_rmin[b * NN + n0 + tid], s_rmin[tid]);
    } else if (tid < 2 * TILE) {
        int j = tid - TILE;
        atomicMin(&g_cmin[b * MM + m0 + j], s_cmin[j]);
    }
}

// -------- finalize: loss = sum(sqrt(cmin))/(B*M) + sum(sqrt(rmin))/(B*N) --------
__global__ void chamfer_finalize_kernel(float* __restrict__ out) {
    __shared__ float red[256];
    int tid = threadIdx.x;
    float sr = 0.f, sc = 0.f;
    for (int i = tid; i < BB * NN; i += 256) sr += sqrtf(__uint_as_float(g_rmin[i]));
    for (int i = tid; i < BB * MM; i += 256) sc += sqrtf(__uint_as_float(g_cmin[i]));
    red[tid] = sr * (1.f / (BB * NN)) + sc * (1.f / (BB * MM));
    __syncthreads();
    for (int o = 128; o > 0; o >>= 1) {
        if (tid < o) red[tid] += red[tid + o];
        __syncthreads();
    }
    if (tid == 0) out[0] = red[0];
}

extern "C" void kernel_launch(void* const* d_in, const int* in_sizes, int n_in,
                              void* d_out, int out_size) {
    const float* X = (const float*)d_in[0];  // [B, N, K]
    const float* Y = (const float*)d_in[1];  // [B, M, K]
    float* out = (float*)d_out;

    const int smem_bytes = 2 * TILE * PAD * sizeof(float);  // 69632
    cudaFuncSetAttribute(chamfer_tile_kernel,
                         cudaFuncAttributeMaxDynamicSharedMemorySize, smem_bytes);

    chamfer_init_kernel<<<(BB * NN + 255) / 256, 256>>>();
    chamfer_sqnorm_kernel<<<(BB * (NN + MM) + 255) / 256, 256>>>(X, Y);

    dim3 grid(MM / TILE, NN / TILE, BB);
    chamfer_tile_kernel<<<grid, 256, smem_bytes>>>(X, Y);

    chamfer_finalize_kernel<<<1, 256>>>(out);
}

// round 3
// speedup vs baseline: 2.3373x; 2.3373x over previous
#include <cuda_runtime.h>
#include <cuda_bf16.h>
#include <cstdint>

#define BB 8
#define NN 4096
#define MM 4096
#define KK 64
#define TILE 128

#define ROWS_X (BB * NN)
#define ROWS_Y (BB * MM)

// ---------------- base-ISA PTX helpers (no 'a'-arch instructions!) ----------------
__device__ __forceinline__ uint32_t smem_to_u32(const void* p) {
    uint32_t a;
    asm("{ .reg .u64 t; cvta.to.shared.u64 t, %1; cvt.u32.u64 %0, t; }" : "=r"(a) : "l"(p));
    return a;
}
__device__ __forceinline__ void ldsm_x4(uint32_t* r, uint32_t addr) {
    asm volatile("ldmatrix.sync.aligned.m8n8.x4.shared.b16 {%0,%1,%2,%3}, [%4];"
                 : "=r"(r[0]), "=r"(r[1]), "=r"(r[2]), "=r"(r[3]) : "r"(addr));
}
__device__ __forceinline__ void mma16816(float* d, const uint32_t* a, const uint32_t* b) {
    asm volatile("mma.sync.aligned.m16n8k16.row.col.f32.bf16.bf16.f32 "
                 "{%0,%1,%2,%3}, {%4,%5,%6,%7}, {%8,%9}, {%0,%1,%2,%3};"
                 : "+f"(d[0]), "+f"(d[1]), "+f"(d[2]), "+f"(d[3])
                 : "r"(a[0]), "r"(a[1]), "r"(a[2]), "r"(a[3]), "r"(b[0]), "r"(b[1]));
}
#define SWZ128(off) ((off) ^ (((off) >> 3) & 0x70))

// ---------------- device scratch (allocation-free) ----------------
__device__ uint4    g_xhi4[ROWS_X * 8];   // 8 uint4 = 64 bf16 per row
__device__ uint4    g_xlo4[ROWS_X * 8];
__device__ uint4    g_yhi4[ROWS_Y * 8];
__device__ uint4    g_ylo4[ROWS_Y * 8];
__device__ float    g_x2[ROWS_X];
__device__ float    g_y2[ROWS_Y];
__device__ unsigned g_rmin[ROWS_X];       // min over m of sq per (b,n)
__device__ unsigned g_cmin[ROWS_Y];       // min over n of sq per (b,m)
__device__ float    g_part[64];

// -------- convert fp32 -> bf16 hi/lo, compute norms, init mins --------
__global__ void chamfer_convert_kernel(const float* __restrict__ X,
                                       const float* __restrict__ Y) {
    int t = blockIdx.x * blockDim.x + threadIdx.x;   // 65536 threads
    const float* src;
    uint4 *hid, *lod;
    float* nrm;
    int idx;
    if (t < ROWS_X) { src = X; hid = g_xhi4; lod = g_xlo4; nrm = g_x2; idx = t; g_rmin[t] = 0x7f800000u; }
    else            { src = Y; hid = g_yhi4; lod = g_ylo4; nrm = g_y2; idx = t - ROWS_X; g_cmin[idx] = 0x7f800000u; }
    const float4* p = reinterpret_cast<const float4*>(src + (size_t)idx * KK);
    hid += (size_t)idx * 8;
    lod += (size_t)idx * 8;
    float s = 0.f;
#pragma unroll
    for (int i = 0; i < 8; ++i) {
        float4 a = p[2 * i], b = p[2 * i + 1];
        s += a.x * a.x + a.y * a.y + a.z * a.z + a.w * a.w;
        s += b.x * b.x + b.y * b.y + b.z * b.z + b.w * b.w;
        float v[8] = {a.x, a.y, a.z, a.w, b.x, b.y, b.z, b.w};
        union { uint4 u; __nv_bfloat162 h[4]; } H, L;
#pragma unroll
        for (int j = 0; j < 4; ++j) {
            __nv_bfloat162 h = __floats2bfloat162_rn(v[2 * j], v[2 * j + 1]);
            float r0 = v[2 * j]     - __bfloat162float(h.x);
            float r1 = v[2 * j + 1] - __bfloat162float(h.y);
            H.h[j] = h;
            L.h[j] = __floats2bfloat162_rn(r0, r1);
        }
        hid[i] = H.u;
        lod[i] = L.u;
    }
    nrm[idx] = s;
}

// -------- main fused mma.sync tile kernel --------
// Grid (MM/128, NN/128, BB), 256 threads = 8 warps laid out 4(m) x 2(n).
// Warp tile 32x64 = 2 mtiles(16) x 8 ntiles(8), fp32 accumulators.
#define TB (TILE * 128)                    // 16384 B per bf16 tile (128 rows x 128 B)
#define OFF_XHI  0
#define OFF_XLO  (OFF_XHI + TB)
#define OFF_YHI  (OFF_XLO + TB)
#define OFF_YLO  (OFF_YHI + TB)
#define OFF_X2   (OFF_YLO + TB)
#define OFF_Y2   (OFF_X2 + 512)
#define OFF_RMIN (OFF_Y2 + 512)
#define OFF_CMIN (OFF_RMIN + 512)
#define SMEM_TOTAL (OFF_CMIN + 512)        // 67584 B

__global__ __launch_bounds__(256, 2)
void chamfer_mma_kernel() {
    extern __shared__ char smem[];
    uint32_t sb = smem_to_u32(smem);
    const int tid = threadIdx.x;
    const int wid = tid >> 5;
    const int lid = tid & 31;
    const int wr  = wid >> 1;     // 0..3 -> m block of 32
    const int wc  = wid & 1;      // 0..1 -> n block of 64
    const int b   = blockIdx.z;
    const int n0  = blockIdx.y * TILE;
    const int m0  = blockIdx.x * TILE;

    float* x2s      = reinterpret_cast<float*>(smem + OFF_X2);
    float* y2s      = reinterpret_cast<float*>(smem + OFF_Y2);
    unsigned* s_rmin = reinterpret_cast<unsigned*>(smem + OFF_RMIN);
    unsigned* s_cmin = reinterpret_cast<unsigned*>(smem + OFF_CMIN);

    if (tid < 128) { x2s[tid] = g_x2[b * NN + n0 + tid]; s_rmin[tid] = 0x7f800000u; }
    else { int j = tid - 128; y2s[j] = g_y2[b * MM + m0 + j]; s_cmin[j] = 0x7f800000u; }

    // Fill 4 bf16 tiles (1024 uint4 each) with 128B-row swizzle.
    {
        const uint4* srcs[4] = {g_xhi4 + (size_t)(b * NN + n0) * 8,
                                g_xlo4 + (size_t)(b * NN + n0) * 8,
                                g_yhi4 + (size_t)(b * MM + m0) * 8,
                                g_ylo4 + (size_t)(b * MM + m0) * 8};
        const int offs[4] = {OFF_XHI, OFF_XLO, OFF_YHI, OFF_YLO};
#pragma unroll
        for (int tgt = 0; tgt < 4; ++tgt) {
            const uint4* s = srcs[tgt];
            char* dbase = smem + offs[tgt];
#pragma unroll
            for (int it = 0; it < 4; ++it) {
                int idx = it * 256 + tid;            // 0..1023
                int r = idx >> 3, q = idx & 7;
                uint32_t off = SWZ128((uint32_t)(r * 128 + q * 16));
                *reinterpret_cast<uint4*>(dbase + off) = s[r * 8 + q];
            }
        }
    }
    __syncthreads();

    float acc[2][8][4];
#pragma unroll
    for (int mt = 0; mt < 2; ++mt)
#pragma unroll
        for (int nt = 0; nt < 8; ++nt)
#pragma unroll
            for (int c = 0; c < 4; ++c) acc[mt][nt][c] = 0.f;

    // 3 passes: hi*hi, hi*lo, lo*hi (lo*lo dropped; ~2^-18 relative)
#pragma unroll
    for (int pass = 0; pass < 3; ++pass) {
        uint32_t Abase = sb + (pass == 2 ? OFF_XLO : OFF_XHI);
        uint32_t Bbase = sb + (pass == 1 ? OFF_YLO : OFF_YHI);
#pragma unroll
        for (int ks = 0; ks < 4; ++ks) {
            uint32_t a[2][4];
#pragma unroll
            for (int mt = 0; mt < 2; ++mt) {
                int row  = wr * 32 + mt * 16 + (lid & 15);
                int colb = ks * 32 + (lid >> 4) * 16;
                uint32_t off = (uint32_t)(row * 128 + (colb ^ ((row & 7) * 16)));
                ldsm_x4(a[mt], Abase + off);
            }
            uint32_t bf[4][4];
#pragma unroll
            for (int j2 = 0; j2 < 4; ++j2) {
                int row  = wc * 64 + j2 * 16 + (lid & 7) + ((lid >> 4) & 1) * 8;
                int colb = ks * 32 + ((lid >> 3) & 1) * 16;
                uint32_t off = (uint32_t)(row * 128 + (colb ^ ((row & 7) * 16)));
                ldsm_x4(bf[j2], Bbase + off);
            }
#pragma unroll
            for (int mt = 0; mt < 2; ++mt)
#pragma unroll
                for (int nt = 0; nt < 8; ++nt)
                    mma16816(acc[mt][nt], a[mt], &bf[nt >> 1][(nt & 1) * 2]);
        }
    }

    // Epilogue: sq = x2 + y2 - 2*dot, clamp, row/col mins.
    // acc[mt][nt][c]: row = wr*32+mt*16+(lid>>2)+8*(c>>1), col = wc*64+nt*8+(lid&3)*2+(c&1)
    float x2v[2][2], y2v[8][2];
#pragma unroll
    for (int mt = 0; mt < 2; ++mt)
#pragma unroll
        for (int h = 0; h < 2; ++h)
            x2v[mt][h] = x2s[wr * 32 + mt * 16 + (lid >> 2) + 8 * h];
#pragma unroll
    for (int nt = 0; nt < 8; ++nt)
#pragma unroll
        for (int p = 0; p < 2; ++p)
            y2v[nt][p] = y2s[wc * 64 + nt * 8 + (lid & 3) * 2 + p];

    float rowm[2][2], colm[8][2];
#pragma unroll
    for (int mt = 0; mt < 2; ++mt)
#pragma unroll
        for (int h = 0; h < 2; ++h) rowm[mt][h] = __int_as_float(0x7f800000);
#pragma unroll
    for (int nt = 0; nt < 8; ++nt)
#pragma unroll
        for (int p = 0; p < 2; ++p) colm[nt][p] = __int_as_float(0x7f800000);

#pragma unroll
    for (int mt = 0; mt < 2; ++mt)
#pragma unroll
        for (int nt = 0; nt < 8; ++nt)
#pragma unroll
            for (int c = 0; c < 4; ++c) {
                int h = c >> 1, p = c & 1;
                float sq = fmaxf(fmaf(-2.f, acc[mt][nt][c], x2v[mt][h] + y2v[nt][p]), 0.f);
                rowm[mt][h] = fminf(rowm[mt][h], sq);
                colm[nt][p] = fminf(colm[nt][p], sq);
            }

    // Row mins: lanes sharing a row differ in bits 0-1 of lid.
#pragma unroll
    for (int mt = 0; mt < 2; ++mt)
#pragma unroll
        for (int h = 0; h < 2; ++h) {
            float v = rowm[mt][h];
            v = fminf(v, __shfl_xor_sync(0xffffffffu, v, 1));
            v = fminf(v, __shfl_xor_sync(0xffffffffu, v, 2));
            if ((lid & 3) == 0)
                atomicMin(&s_rmin[wr * 32 + mt * 16 + (lid >> 2) + 8 * h], __float_as_uint(v));
        }
    // Col mins: lanes sharing a col differ in bits 2-4 of lid.
#pragma unroll
    for (int nt = 0; nt < 8; ++nt)
#pragma unroll
        for (int p = 0; p < 2; ++p) {
            float v = colm[nt][p];
            v = fminf(v, __shfl_xor_sync(0xffffffffu, v, 4));
            v = fminf(v, __shfl_xor_sync(0xffffffffu, v, 8));
            v = fminf(v, __shfl_xor_sync(0xffffffffu, v, 16));
            if (lid < 4)
                atomicMin(&s_cmin[wc * 64 + nt * 8 + (lid & 3) * 2 + p], __float_as_uint(v));
        }

    __syncthreads();
    if (tid < 128) atomicMin(&g_rmin[b * NN + n0 + tid], s_rmin[tid]);
    else           atomicMin(&g_cmin[b * MM + m0 + (tid - 128)], s_cmin[tid - 128]);
}

// -------- parallel finalize: 64-block partials, then tiny final reduce --------
__global__ void chamfer_partial_kernel() {
    __shared__ float red[256];
    const int blk = blockIdx.x, tid = threadIdx.x;
    const int base = blk * 512;
    float s = 0.f;
#pragma unroll
    for (int i = tid; i < 512; i += 256)
        s += sqrtf(__uint_as_float(g_rmin[base + i])) * (1.f / (float)ROWS_X);
#pragma unroll
    for (int i = tid; i < 512; i += 256)
        s += sqrtf(__uint_as_float(g_cmin[base + i])) * (1.f / (float)ROWS_Y);
    red[tid] = s;
    __syncthreads();
    for (int o = 128; o > 0; o >>= 1) {
        if (tid < o) red[tid] += red[tid + o];
        __syncthreads();
    }
    if (tid == 0) g_part[blk] = red[0];
}

__global__ void chamfer_final_kernel(float* __restrict__ out) {
    __shared__ float red[64];
    int tid = threadIdx.x;
    red[tid] = g_part[tid];
    __syncthreads();
    for (int o = 32; o > 0; o >>= 1) {
        if (tid < o) red[tid] += red[tid + o];
        __syncthreads();
    }
    if (tid == 0) out[0] = red[0];
}

extern "C" void kernel_launch(void* const* d_in, const int* in_sizes, int n_in,
                              void* d_out, int out_size) {
    const float* X = (const float*)d_in[0];  // [B, N, K]
    const float* Y = (const float*)d_in[1];  // [B, M, K]
    float* out = (float*)d_out;

    cudaFuncSetAttribute(chamfer_mma_kernel,
                         cudaFuncAttributeMaxDynamicSharedMemorySize, SMEM_TOTAL);

    chamfer_convert_kernel<<<(ROWS_X + ROWS_Y) / 256, 256>>>(X, Y);
    dim3 grid(MM / TILE, NN / TILE, BB);
    chamfer_mma_kernel<<<grid, 256, SMEM_TOTAL>>>();
    chamfer_partial_kernel<<<64, 256>>>();
    chamfer_final_kernel<<<1, 64>>>(out);
}

// round 4
// speedup vs baseline: 3.3523x; 1.4342x over previous
#include <cuda_runtime.h>
#include <cuda_fp16.h>
#include <cstdint>

#define BB 8
#define NN 4096
#define MM 4096
#define KK 64
#define TILE 128

#define ROWS_X (BB * NN)
#define ROWS_Y (BB * MM)

// ---------------- base-ISA PTX helpers ----------------
__device__ __forceinline__ uint32_t smem_to_u32(const void* p) {
    uint32_t a;
    asm("{ .reg .u64 t; cvta.to.shared.u64 t, %1; cvt.u32.u64 %0, t; }" : "=r"(a) : "l"(p));
    return a;
}
__device__ __forceinline__ void ldsm_x4(uint32_t* r, uint32_t addr) {
    asm volatile("ldmatrix.sync.aligned.m8n8.x4.shared.b16 {%0,%1,%2,%3}, [%4];"
                 : "=r"(r[0]), "=r"(r[1]), "=r"(r[2]), "=r"(r[3]) : "r"(addr));
}
__device__ __forceinline__ void mma16816(float* d, const uint32_t* a, const uint32_t* b) {
    asm volatile("mma.sync.aligned.m16n8k16.row.col.f32.f16.f16.f32 "
                 "{%0,%1,%2,%3}, {%4,%5,%6,%7}, {%8,%9}, {%0,%1,%2,%3};"
                 : "+f"(d[0]), "+f"(d[1]), "+f"(d[2]), "+f"(d[3])
                 : "r"(a[0]), "r"(a[1]), "r"(a[2]), "r"(a[3]), "r"(b[0]), "r"(b[1]));
}
#define SWZ128(off) ((off) ^ (((off) >> 3) & 0x70))

// ---------------- device scratch (allocation-free) ----------------
__device__ uint4    g_xh4[ROWS_X * 8];    // 8 uint4 = 64 fp16 per row
__device__ uint4    g_yh4[ROWS_Y * 8];
__device__ float    g_x2[ROWS_X];
__device__ float    g_y2[ROWS_Y];
__device__ unsigned g_rmin[ROWS_X];       // packed (sq|m) per (b,n)
__device__ unsigned g_cmin[ROWS_Y];       // packed (sq|n) per (b,m)
__device__ float    g_part[256];

// -------- convert fp32 -> fp16, compute exact fp32 norms, init keys --------
__global__ void chamfer_convert_kernel(const float* __restrict__ X,
                                       const float* __restrict__ Y) {
    int t = blockIdx.x * blockDim.x + threadIdx.x;   // 65536 threads
    const float* src;
    uint4* hd;
    float* nrm;
    int idx;
    if (t < ROWS_X) { src = X; hd = g_xh4; nrm = g_x2; idx = t; g_rmin[t] = 0xFFFFFFFFu; }
    else            { src = Y; hd = g_yh4; nrm = g_y2; idx = t - ROWS_X; g_cmin[idx] = 0xFFFFFFFFu; }
    const float4* p = reinterpret_cast<const float4*>(src + (size_t)idx * KK);
    hd += (size_t)idx * 8;
    float s = 0.f;
#pragma unroll
    for (int i = 0; i < 8; ++i) {
        float4 a = p[2 * i], b = p[2 * i + 1];
        s += a.x * a.x + a.y * a.y + a.z * a.z + a.w * a.w;
        s += b.x * b.x + b.y * b.y + b.z * b.z + b.w * b.w;
        union { uint4 u; __half2 h[4]; } H;
        H.h[0] = __floats2half2_rn(a.x, a.y);
        H.h[1] = __floats2half2_rn(a.z, a.w);
        H.h[2] = __floats2half2_rn(b.x, b.y);
        H.h[3] = __floats2half2_rn(b.z, b.w);
        hd[i] = H.u;
    }
    nrm[idx] = s;
}

// -------- main fused mma.sync tile kernel (single fp16 pass, argmin keys) --------
// Grid (MM/128, NN/128, BB), 256 threads = 8 warps laid out 4(m) x 2(n).
#define TB (TILE * 128)                    // 16384 B per fp16 tile
#define OFF_XT   0
#define OFF_YT   (OFF_XT + TB)
#define OFF_X2   (OFF_YT + TB)
#define OFF_Y2   (OFF_X2 + 512)
#define OFF_RMIN (OFF_Y2 + 512)
#define OFF_CMIN (OFF_RMIN + 512)
#define SMEM_TOTAL (OFF_CMIN + 512)        // 34816 B

__global__ __launch_bounds__(256, 2)
void chamfer_mma_kernel() {
    extern __shared__ char smem[];
    uint32_t sb = smem_to_u32(smem);
    const int tid = threadIdx.x;
    const int wid = tid >> 5;
    const int lid = tid & 31;
    const int wr  = wid >> 1;     // m block of 32
    const int wc  = wid & 1;      // n block of 64
    const int b   = blockIdx.z;
    const int n0  = blockIdx.y * TILE;
    const int m0  = blockIdx.x * TILE;

    float* x2s       = reinterpret_cast<float*>(smem + OFF_X2);
    float* y2s       = reinterpret_cast<float*>(smem + OFF_Y2);
    unsigned* s_rmin = reinterpret_cast<unsigned*>(smem + OFF_RMIN);
    unsigned* s_cmin = reinterpret_cast<unsigned*>(smem + OFF_CMIN);

    if (tid < 128) { x2s[tid] = g_x2[b * NN + n0 + tid]; s_rmin[tid] = 0xFFFFFFFFu; }
    else { int j = tid - 128; y2s[j] = g_y2[b * MM + m0 + j]; s_cmin[j] = 0xFFFFFFFFu; }

    // Fill 2 fp16 tiles (1024 uint4 each) with 128B-row swizzle.
    {
        const uint4* sx = g_xh4 + (size_t)(b * NN + n0) * 8;
        const uint4* sy = g_yh4 + (size_t)(b * MM + m0) * 8;
#pragma unroll
        for (int it = 0; it < 4; ++it) {
            int idx = it * 256 + tid;            // 0..1023
            int r = idx >> 3, q = idx & 7;
            uint32_t off = SWZ128((uint32_t)(r * 128 + q * 16));
            *reinterpret_cast<uint4*>(smem + OFF_XT + off) = sx[r * 8 + q];
            *reinterpret_cast<uint4*>(smem + OFF_YT + off) = sy[r * 8 + q];
        }
    }
    __syncthreads();

    float acc[2][8][4];
#pragma unroll
    for (int mt = 0; mt < 2; ++mt)
#pragma unroll
        for (int nt = 0; nt < 8; ++nt)
#pragma unroll
            for (int c = 0; c < 4; ++c) acc[mt][nt][c] = 0.f;

#pragma unroll
    for (int ks = 0; ks < 4; ++ks) {
        uint32_t a[2][4];
#pragma unroll
        for (int mt = 0; mt < 2; ++mt) {
            int row  = wr * 32 + mt * 16 + (lid & 15);
            int colb = ks * 32 + (lid >> 4) * 16;
            uint32_t off = (uint32_t)(row * 128 + (colb ^ ((row & 7) * 16)));
            ldsm_x4(a[mt], sb + OFF_XT + off);
        }
        uint32_t bf[4][4];
#pragma unroll
        for (int j2 = 0; j2 < 4; ++j2) {
            int row  = wc * 64 + j2 * 16 + (lid & 7) + ((lid >> 4) & 1) * 8;
            int colb = ks * 32 + ((lid >> 3) & 1) * 16;
            uint32_t off = (uint32_t)(row * 128 + (colb ^ ((row & 7) * 16)));
            ldsm_x4(bf[j2], sb + OFF_YT + off);
        }
#pragma unroll
        for (int mt = 0; mt < 2; ++mt)
#pragma unroll
            for (int nt = 0; nt < 8; ++nt)
                mma16816(acc[mt][nt], a[mt], &bf[nt >> 1][(nt & 1) * 2]);
    }

    // Epilogue: approx sq -> packed argmin keys.
    // acc[mt][nt][c]: row = wr*32+mt*16+(lid>>2)+8*(c>>1), col = wc*64+nt*8+(lid&3)*2+(c&1)
    float x2v[2][2], y2v[8][2];
#pragma unroll
    for (int mt = 0; mt < 2; ++mt)
#pragma unroll
        for (int h = 0; h < 2; ++h)
            x2v[mt][h] = x2s[wr * 32 + mt * 16 + (lid >> 2) + 8 * h];
#pragma unroll
    for (int nt = 0; nt < 8; ++nt)
#pragma unroll
        for (int p = 0; p < 2; ++p)
            y2v[nt][p] = y2s[wc * 64 + nt * 8 + (lid & 3) * 2 + p];

    unsigned rowm[2][2], colm[8][2];
#pragma unroll
    for (int mt = 0; mt < 2; ++mt)
#pragma unroll
        for (int h = 0; h < 2; ++h) rowm[mt][h] = 0xFFFFFFFFu;
#pragma unroll
    for (int nt = 0; nt < 8; ++nt)
#pragma unroll
        for (int p = 0; p < 2; ++p) colm[nt][p] = 0xFFFFFFFFu;

#pragma unroll
    for (int mt = 0; mt < 2; ++mt)
#pragma unroll
        for (int nt = 0; nt < 8; ++nt)
#pragma unroll
            for (int c = 0; c < 4; ++c) {
                int h = c >> 1, p = c & 1;
                float sq = fmaxf(fmaf(-2.f, acc[mt][nt][c], x2v[mt][h] + y2v[nt][p]), 0.f);
                unsigned tbits = __float_as_uint(sq) & 0xFFFFF000u;
                unsigned mcol = (unsigned)(m0 + wc * 64 + nt * 8 + (lid & 3) * 2 + p);
                unsigned nrow = (unsigned)(n0 + wr * 32 + mt * 16 + (lid >> 2) + 8 * h);
                rowm[mt][h] = min(rowm[mt][h], tbits | mcol);
                colm[nt][p] = min(colm[nt][p], tbits | nrow);
            }

    // Row keys: lanes sharing a row differ in bits 0-1 of lid.
#pragma unroll
    for (int mt = 0; mt < 2; ++mt)
#pragma unroll
        for (int h = 0; h < 2; ++h) {
            unsigned v = rowm[mt][h];
            v = min(v, __shfl_xor_sync(0xffffffffu, v, 1));
            v = min(v, __shfl_xor_sync(0xffffffffu, v, 2));
            if ((lid & 3) == 0)
                atomicMin(&s_rmin[wr * 32 + mt * 16 + (lid >> 2) + 8 * h], v);
        }
    // Col keys: lanes sharing a col differ in bits 2-4 of lid.
#pragma unroll
    for (int nt = 0; nt < 8; ++nt)
#pragma unroll
        for (int p = 0; p < 2; ++p) {
            unsigned v = colm[nt][p];
            v = min(v, __shfl_xor_sync(0xffffffffu, v, 4));
            v = min(v, __shfl_xor_sync(0xffffffffu, v, 8));
            v = min(v, __shfl_xor_sync(0xffffffffu, v, 16));
            if (lid < 4)
                atomicMin(&s_cmin[wc * 64 + nt * 8 + (lid & 3) * 2 + p], v);
        }

    __syncthreads();
    if (tid < 128) atomicMin(&g_rmin[b * NN + n0 + tid], s_rmin[tid]);
    else           atomicMin(&g_cmin[b * MM + m0 + (tid - 128)], s_cmin[tid - 128]);
}

// -------- recompute exact distances for selected pairs + partial reduce --------
__global__ void chamfer_recompute_kernel(const float* __restrict__ X,
                                         const float* __restrict__ Y) {
    __shared__ float red[256];
    const int tid = threadIdx.x;
    const int t = blockIdx.x * 256 + tid;     // 0..65535
    const float* xp;
    const float* yp;
    if (t < ROWS_X) {                          // row side: (b,n) -> argmin m
        int b = t >> 12, n = t & 4095;
        int m = (int)(g_rmin[t] & 0xFFFu);
        xp = X + ((size_t)(b * NN + n)) * KK;
        yp = Y + ((size_t)(b * MM + m)) * KK;
    } else {                                   // col side: (b,m) -> argmin n
        int u = t - ROWS_X;
        int b = u >> 12, m = u & 4095;
        int n = (int)(g_cmin[u] & 0xFFFu);
        xp = X + ((size_t)(b * NN + n)) * KK;
        yp = Y + ((size_t)(b * MM + m)) * KK;
    }
    const float4* px = reinterpret_cast<const float4*>(xp);
    const float4* py = reinterpret_cast<const float4*>(yp);
    float s = 0.f;
#pragma unroll
    for (int i = 0; i < KK / 4; ++i) {
        float4 a = px[i], c = py[i];
        float dx = a.x - c.x, dy = a.y - c.y, dz = a.z - c.z, dw = a.w - c.w;
        s += dx * dx + dy * dy + dz * dz + dw * dw;
    }
    red[tid] = sqrtf(s) * (1.f / (float)ROWS_X);   // both sides divide by 32768
    __syncthreads();
    for (int o = 128; o > 0; o >>= 1) {
        if (tid < o) red[tid] += red[tid + o];
        __syncthreads();
    }
    if (tid == 0) g_part[blockIdx.x] = red[0];
}

__global__ void chamfer_final_kernel(float* __restrict__ out) {
    __shared__ float red[256];
    int tid = threadIdx.x;
    red[tid] = g_part[tid];
    __syncthreads();
    for (int o = 128; o > 0; o >>= 1) {
        if (tid < o) red[tid] += red[tid + o];
        __syncthreads();
    }
    if (tid == 0) out[0] = red[0];
}

extern "C" void kernel_launch(void* const* d_in, const int* in_sizes, int n_in,
                              void* d_out, int out_size) {
    const float* X = (const float*)d_in[0];  // [B, N, K]
    const float* Y = (const float*)d_in[1];  // [B, M, K]
    float* out = (float*)d_out;

    cudaFuncSetAttribute(chamfer_mma_kernel,
                         cudaFuncAttributeMaxDynamicSharedMemorySize, SMEM_TOTAL);

    chamfer_convert_kernel<<<(ROWS_X + ROWS_Y) / 256, 256>>>(X, Y);
    dim3 grid(MM / TILE, NN / TILE, BB);
    chamfer_mma_kernel<<<grid, 256, SMEM_TOTAL>>>();
    chamfer_recompute_kernel<<<256, 256>>>(X, Y);
    chamfer_final_kernel<<<1, 256>>>(out);
}

// round 5
// speedup vs baseline: 3.7427x; 1.1165x over previous
#include <cuda_runtime.h>
#include <cuda_fp16.h>
#include <cstdint>

#define BB 8
#define NN 4096
#define MM 4096
#define KK 64
#define TILE 128
#define MT 4                               // m-tiles per CTA

#define ROWS_X (BB * NN)
#define ROWS_Y (BB * MM)

// ---------------- base-ISA PTX helpers ----------------
__device__ __forceinline__ uint32_t smem_to_u32(const void* p) {
    uint32_t a;
    asm("{ .reg .u64 t; cvta.to.shared.u64 t, %1; cvt.u32.u64 %0, t; }" : "=r"(a) : "l"(p));
    return a;
}
__device__ __forceinline__ void ldsm_x4(uint32_t* r, uint32_t addr) {
    asm volatile("ldmatrix.sync.aligned.m8n8.x4.shared.b16 {%0,%1,%2,%3}, [%4];"
                 : "=r"(r[0]), "=r"(r[1]), "=r"(r[2]), "=r"(r[3]) : "r"(addr));
}
__device__ __forceinline__ void mma16816(float* d, const uint32_t* a, const uint32_t* b) {
    asm volatile("mma.sync.aligned.m16n8k16.row.col.f32.f16.f16.f32 "
                 "{%0,%1,%2,%3}, {%4,%5,%6,%7}, {%8,%9}, {%0,%1,%2,%3};"
                 : "+f"(d[0]), "+f"(d[1]), "+f"(d[2]), "+f"(d[3])
                 : "r"(a[0]), "r"(a[1]), "r"(a[2]), "r"(a[3]), "r"(b[0]), "r"(b[1]));
}
__device__ __forceinline__ void cp_async16(uint32_t dst, const void* src) {
    asm volatile("cp.async.cg.shared.global [%0], [%1], 16;" :: "r"(dst), "l"(src) : "memory");
}
#define CP_COMMIT() asm volatile("cp.async.commit_group;" ::: "memory")
#define CP_WAIT(N)  asm volatile("cp.async.wait_group %0;" :: "n"(N) : "memory")
#define SWZ128(off) ((off) ^ (((off) >> 3) & 0x70))

// ---------------- device scratch (allocation-free) ----------------
__device__ uint4    g_xh4[ROWS_X * 8];    // 8 uint4 = 64 fp16 per row
__device__ uint4    g_yh4[ROWS_Y * 8];
__device__ float    g_x2[ROWS_X];
__device__ float    g_y2[ROWS_Y];
__device__ unsigned g_rmin[ROWS_X];       // packed (sq|m) per (b,n)
__device__ unsigned g_cmin[ROWS_Y];       // packed (sq|n) per (b,m)
__device__ float    g_part[256];

// -------- convert fp32 -> fp16, compute exact fp32 norms, init keys --------
__global__ void chamfer_convert_kernel(const float* __restrict__ X,
                                       const float* __restrict__ Y) {
    int t = blockIdx.x * blockDim.x + threadIdx.x;   // 65536 threads
    const float* src;
    uint4* hd;
    float* nrm;
    int idx;
    if (t < ROWS_X) { src = X; hd = g_xh4; nrm = g_x2; idx = t; g_rmin[t] = 0xFFFFFFFFu; }
    else            { src = Y; hd = g_yh4; nrm = g_y2; idx = t - ROWS_X; g_cmin[idx] = 0xFFFFFFFFu; }
    const float4* p = reinterpret_cast<const float4*>(src + (size_t)idx * KK);
    hd += (size_t)idx * 8;
    float s = 0.f;
#pragma unroll
    for (int i = 0; i < 8; ++i) {
        float4 a = p[2 * i], b = p[2 * i + 1];
        s += a.x * a.x + a.y * a.y + a.z * a.z + a.w * a.w;
        s += b.x * b.x + b.y * b.y + b.z * b.z + b.w * b.w;
        union { uint4 u; __half2 h[4]; } H;
        H.h[0] = __floats2half2_rn(a.x, a.y);
        H.h[1] = __floats2half2_rn(a.z, a.w);
        H.h[2] = __floats2half2_rn(b.x, b.y);
        H.h[3] = __floats2half2_rn(b.z, b.w);
        hd[i] = H.u;
    }
    nrm[idx] = s;
}

// -------- main fused mma.sync kernel: persistent X tile, loop over 4 Y tiles --------
// Grid (MM/(128*MT), NN/128, BB) = (8, 32, 8). 256 threads = 8 warps, 4(m) x 2(n).
#define TB (TILE * 128)                    // 16384 B per fp16 tile
#define OFF_XT   0
#define OFF_YT0  (OFF_XT + TB)
#define OFF_YT1  (OFF_YT0 + TB)
#define OFF_X2   (OFF_YT1 + TB)
#define OFF_Y20  (OFF_X2 + 512)
#define OFF_Y21  (OFF_Y20 + 512)
#define OFF_CMIN (OFF_Y21 + 512)
#define SMEM_TOTAL (OFF_CMIN + 512)        // 51200 B

__global__ __launch_bounds__(256, 2)
void chamfer_mma_kernel() {
    extern __shared__ char smem[];
    uint32_t sb = smem_to_u32(smem);
    const int tid = threadIdx.x;
    const int wid = tid >> 5;
    const int lid = tid & 31;
    const int wr  = wid >> 1;     // m block of 32
    const int wc  = wid & 1;      // n block of 64
    const int b   = blockIdx.z;
    const int n0  = blockIdx.y * TILE;
    const int m0b = blockIdx.x * (TILE * MT);

    float*    x2s    = reinterpret_cast<float*>(smem + OFF_X2);
    unsigned* s_cmin = reinterpret_cast<unsigned*>(smem + OFF_CMIN);
    float*    y2sbuf[2] = {reinterpret_cast<float*>(smem + OFF_Y20),
                           reinterpret_cast<float*>(smem + OFF_Y21)};
    const uint32_t ytb[2] = {sb + OFF_YT0, sb + OFF_YT1};

    // thread's fill mapping (4 uint4 per tile)
    const int fr0 = tid >> 3;              // rows tid/8 + {0,32,64,96}
    const int fq  = tid & 7;
    uint32_t fdst[4];
    size_t   fsrc[4];
#pragma unroll
    for (int it = 0; it < 4; ++it) {
        int r = fr0 + it * 32;
        fdst[it] = SWZ128((uint32_t)(r * 128 + fq * 16));
        fsrc[it] = (size_t)r * 8 + fq;
    }

    // prologue: group0 = {X, Y0}, group1 = {Y1}
    const uint4* sx = g_xh4 + (size_t)(b * NN + n0) * 8;
    const uint4* sy = g_yh4 + (size_t)(b * MM + m0b) * 8;
#pragma unroll
    for (int it = 0; it < 4; ++it) cp_async16(sb + OFF_XT + fdst[it], sx + fsrc[it]);
#pragma unroll
    for (int it = 0; it < 4; ++it) cp_async16(ytb[0] + fdst[it], sy + fsrc[it]);
    CP_COMMIT();
#pragma unroll
    for (int it = 0; it < 4; ++it) cp_async16(ytb[1] + fdst[it], sy + 1024 + fsrc[it]);
    CP_COMMIT();

    if (tid < 128) { x2s[tid] = g_x2[b * NN + n0 + tid]; s_cmin[tid] = 0xFFFFFFFFu; }
    else {
        int j = tid - 128;
        y2sbuf[0][j] = g_y2[b * MM + m0b + j];
        y2sbuf[1][j] = g_y2[b * MM + m0b + 128 + j];
    }

    unsigned rowm[2][2];
#pragma unroll
    for (int mt = 0; mt < 2; ++mt)
#pragma unroll
        for (int h = 0; h < 2; ++h) rowm[mt][h] = 0xFFFFFFFFu;

    float x2v[2][2];   // loaded after first sync

#pragma unroll
    for (int t = 0; t < MT; ++t) {
        if (t < MT - 1) { CP_WAIT(1); } else { CP_WAIT(0); }
        __syncthreads();
        if (t == 0) {
#pragma unroll
            for (int mt = 0; mt < 2; ++mt)
#pragma unroll
                for (int h = 0; h < 2; ++h)
                    x2v[mt][h] = x2s[wr * 32 + mt * 16 + (lid >> 2) + 8 * h];
        }

        const uint32_t Yb = ytb[t & 1];
        const float* y2s  = y2sbuf[t & 1];

        float acc[2][8][4];
#pragma unroll
        for (int mt = 0; mt < 2; ++mt)
#pragma unroll
            for (int nt = 0; nt < 8; ++nt)
#pragma unroll
                for (int c = 0; c < 4; ++c) acc[mt][nt][c] = 0.f;

#pragma unroll
        for (int ks = 0; ks < 4; ++ks) {
            uint32_t a[2][4];
#pragma unroll
            for (int mt = 0; mt < 2; ++mt) {
                int row  = wr * 32 + mt * 16 + (lid & 15);
                int colb = ks * 32 + (lid >> 4) * 16;
                uint32_t off = (uint32_t)(row * 128 + (colb ^ ((row & 7) * 16)));
                ldsm_x4(a[mt], sb + OFF_XT + off);
            }
            uint32_t bf[4][4];
#pragma unroll
            for (int j2 = 0; j2 < 4; ++j2) {
                int row  = wc * 64 + j2 * 16 + (lid & 7) + ((lid >> 4) & 1) * 8;
                int colb = ks * 32 + ((lid >> 3) & 1) * 16;
                uint32_t off = (uint32_t)(row * 128 + (colb ^ ((row & 7) * 16)));
                ldsm_x4(bf[j2], Yb + off);
            }
#pragma unroll
            for (int mt = 0; mt < 2; ++mt)
#pragma unroll
                for (int nt = 0; nt < 8; ++nt)
                    mma16816(acc[mt][nt], a[mt], &bf[nt >> 1][(nt & 1) * 2]);
        }

        // epilogue: packed argmin keys
        const int m0 = m0b + t * TILE;
        float y2v[8][2];
#pragma unroll
        for (int nt = 0; nt < 8; ++nt)
#pragma unroll
            for (int p = 0; p < 2; ++p)
                y2v[nt][p] = y2s[wc * 64 + nt * 8 + (lid & 3) * 2 + p];

        unsigned colm[8][2];
#pragma unroll
        for (int nt = 0; nt < 8; ++nt)
#pragma unroll
            for (int p = 0; p < 2; ++p) colm[nt][p] = 0xFFFFFFFFu;

#pragma unroll
        for (int mt = 0; mt < 2; ++mt)
#pragma unroll
            for (int nt = 0; nt < 8; ++nt)
#pragma unroll
                for (int c = 0; c < 4; ++c) {
                    int h = c >> 1, p = c & 1;
                    float sq = fmaxf(fmaf(-2.f, acc[mt][nt][c], x2v[mt][h] + y2v[nt][p]), 0.f);
                    unsigned tbits = __float_as_uint(sq) & 0xFFFFF000u;
                    unsigned mcol = (unsigned)(m0 + wc * 64 + nt * 8 + (lid & 3) * 2 + p);
                    unsigned nrow = (unsigned)(n0 + wr * 32 + mt * 16 + (lid >> 2) + 8 * h);
                    rowm[mt][h] = min(rowm[mt][h], tbits | mcol);
                    colm[nt][p] = min(colm[nt][p], tbits | nrow);
                }

        // col keys -> smem (lanes sharing a col differ in lid bits 2-4)
#pragma unroll
        for (int nt = 0; nt < 8; ++nt)
#pragma unroll
            for (int p = 0; p < 2; ++p) {
                unsigned v = colm[nt][p];
                v = min(v, __shfl_xor_sync(0xffffffffu, v, 4));
                v = min(v, __shfl_xor_sync(0xffffffffu, v, 8));
                v = min(v, __shfl_xor_sync(0xffffffffu, v, 16));
                if (lid < 4)
                    atomicMin(&s_cmin[wc * 64 + nt * 8 + (lid & 3) * 2 + p], v);
            }
        __syncthreads();

        // flush col keys, reset, and prefetch Y_{t+2}
        if (tid < 128) {
            atomicMin(&g_cmin[b * MM + m0 + tid], s_cmin[tid]);
            s_cmin[tid] = 0xFFFFFFFFu;
        }
        if (t < MT - 2) {
#pragma unroll
            for (int it = 0; it < 4; ++it)
                cp_async16(ytb[t & 1] + fdst[it], sy + (size_t)(t + 2) * 1024 + fsrc[it]);
            CP_COMMIT();
            if (tid >= 128) {
                int j = tid - 128;
                y2sbuf[t & 1][j] = g_y2[b * MM + m0b + (t + 2) * 128 + j];
            }
        }
    }

    // row keys: accumulated over all 4 m-tiles; flush once (lid bits 0-1 share a row)
#pragma unroll
    for (int mt = 0; mt < 2; ++mt)
#pragma unroll
        for (int h = 0; h < 2; ++h) {
            unsigned v = rowm[mt][h];
            v = min(v, __shfl_xor_sync(0xffffffffu, v, 1));
            v = min(v, __shfl_xor_sync(0xffffffffu, v, 2));
            if ((lid & 3) == 0)
                atomicMin(&g_rmin[b * NN + n0 + wr * 32 + mt * 16 + (lid >> 2) + 8 * h], v);
        }
}

// -------- recompute exact distances for selected pairs + partial reduce --------
__global__ void chamfer_recompute_kernel(const float* __restrict__ X,
                                         const float* __restrict__ Y) {
    __shared__ float red[256];
    const int tid = threadIdx.x;
    const int t = blockIdx.x * 256 + tid;     // 0..65535
    const float* xp;
    const float* yp;
    if (t < ROWS_X) {                          // row side: (b,n) -> argmin m
        int b = t >> 12, n = t & 4095;
        int m = (int)(g_rmin[t] & 0xFFFu);
        xp = X + ((size_t)(b * NN + n)) * KK;
        yp = Y + ((size_t)(b * MM + m)) * KK;
    } else {                                   // col side: (b,m) -> argmin n
        int u = t - ROWS_X;
        int b = u >> 12, m = u & 4095;
        int n = (int)(g_cmin[u] & 0xFFFu);
        xp = X + ((size_t)(b * NN + n)) * KK;
        yp = Y + ((size_t)(b * MM + m)) * KK;
    }
    const float4* px = reinterpret_cast<const float4*>(xp);
    const float4* py = reinterpret_cast<const float4*>(yp);
    float s = 0.f;
#pragma unroll
    for (int i = 0; i < KK / 4; ++i) {
        float4 a = px[i], c = py[i];
        float dx = a.x - c.x, dy = a.y - c.y, dz = a.z - c.z, dw = a.w - c.w;
        s += dx * dx + dy * dy + dz * dz + dw * dw;
    }
    red[tid] = sqrtf(s) * (1.f / (float)ROWS_X);   // both sides divide by 32768
    __syncthreads();
    for (int o = 128; o > 0; o >>= 1) {
        if (tid < o) red[tid] += red[tid + o];
        __syncthreads();
    }
    if (tid == 0) g_part[blockIdx.x] = red[0];
}

__global__ void chamfer_final_kernel(float* __restrict__ out) {
    __shared__ float red[256];
    int tid = threadIdx.x;
    red[tid] = g_part[tid];
    __syncthreads();
    for (int o = 128; o > 0; o >>= 1) {
        if (tid < o) red[tid] += red[tid + o];
        __syncthreads();
    }
    if (tid == 0) out[0] = red[0];
}

extern "C" void kernel_launch(void* const* d_in, const int* in_sizes, int n_in,
                              void* d_out, int out_size) {
    const float* X = (const float*)d_in[0];  // [B, N, K]
    const float* Y = (const float*)d_in[1];  // [B, M, K]
    float* out = (float*)d_out;

    cudaFuncSetAttribute(chamfer_mma_kernel,
                         cudaFuncAttributeMaxDynamicSharedMemorySize, SMEM_TOTAL);

    chamfer_convert_kernel<<<(ROWS_X + ROWS_Y) / 256, 256>>>(X, Y);
    dim3 grid(MM / (TILE * MT), NN / TILE, BB);
    chamfer_mma_kernel<<<grid, 256, SMEM_TOTAL>>>();
    chamfer_recompute_kernel<<<256, 256>>>(X, Y);
    chamfer_final_kernel<<<1, 256>>>(out);
}

// round 6
// speedup vs baseline: 4.8642x; 1.2997x over previous
#include <cuda_runtime.h>
#include <cuda_fp16.h>
#include <cstdint>

#define BB 8
#define NN 4096
#define MM 4096
#define KK 64
#define TILE 128
#define MT 4                               // m-tiles per CTA

#define ROWS_X (BB * NN)
#define ROWS_Y (BB * MM)

// ---------------- base-ISA PTX helpers ----------------
__device__ __forceinline__ uint32_t smem_to_u32(const void* p) {
    uint32_t a;
    asm("{ .reg .u64 t; cvta.to.shared.u64 t, %1; cvt.u32.u64 %0, t; }" : "=r"(a) : "l"(p));
    return a;
}
__device__ __forceinline__ void ldsm_x4(uint32_t* r, uint32_t addr) {
    asm volatile("ldmatrix.sync.aligned.m8n8.x4.shared.b16 {%0,%1,%2,%3}, [%4];"
                 : "=r"(r[0]), "=r"(r[1]), "=r"(r[2]), "=r"(r[3]) : "r"(addr));
}
__device__ __forceinline__ void mma16816(float* d, const uint32_t* a, const uint32_t* b) {
    asm volatile("mma.sync.aligned.m16n8k16.row.col.f32.f16.f16.f32 "
                 "{%0,%1,%2,%3}, {%4,%5,%6,%7}, {%8,%9}, {%0,%1,%2,%3};"
                 : "+f"(d[0]), "+f"(d[1]), "+f"(d[2]), "+f"(d[3])
                 : "r"(a[0]), "r"(a[1]), "r"(a[2]), "r"(a[3]), "r"(b[0]), "r"(b[1]));
}
__device__ __forceinline__ void cp_async16(uint32_t dst, const void* src) {
    asm volatile("cp.async.cg.shared.global [%0], [%1], 16;" :: "r"(dst), "l"(src) : "memory");
}
#define CP_COMMIT() asm volatile("cp.async.commit_group;" ::: "memory")
#define CP_WAIT(N)  asm volatile("cp.async.wait_group %0;" :: "n"(N) : "memory")
#define SWZ128(off) ((off) ^ (((off) >> 3) & 0x70))

// ---------------- device scratch (allocation-free) ----------------
__device__ uint4    g_xh4[ROWS_X * 8];    // 8 uint4 = 64 fp16 per row
__device__ uint4    g_yh4[ROWS_Y * 8];
__device__ float    g_x2[ROWS_X];
__device__ float    g_y2[ROWS_Y];
__device__ unsigned g_rmin[ROWS_X];       // fp32 bits of min clamped sq per (b,n)
__device__ unsigned g_cmin[ROWS_Y];       // fp32 bits of min clamped sq per (b,m)
__device__ float    g_part[256];

// -------- convert fp32 -> fp16, compute exact fp32 norms, init mins --------
__global__ void chamfer_convert_kernel(const float* __restrict__ X,
                                       const float* __restrict__ Y) {
    int t = blockIdx.x * blockDim.x + threadIdx.x;   // 65536 threads
    const float* src;
    uint4* hd;
    float* nrm;
    int idx;
    if (t < ROWS_X) { src = X; hd = g_xh4; nrm = g_x2; idx = t; g_rmin[t] = 0x7f800000u; }
    else            { src = Y; hd = g_yh4; nrm = g_y2; idx = t - ROWS_X; g_cmin[idx] = 0x7f800000u; }
    const float4* p = reinterpret_cast<const float4*>(src + (size_t)idx * KK);
    hd += (size_t)idx * 8;
    float s = 0.f;
#pragma unroll
    for (int i = 0; i < 8; ++i) {
        float4 a = p[2 * i], b = p[2 * i + 1];
        s += a.x * a.x + a.y * a.y + a.z * a.z + a.w * a.w;
        s += b.x * b.x + b.y * b.y + b.z * b.z + b.w * b.w;
        union { uint4 u; __half2 h[4]; } H;
        H.h[0] = __floats2half2_rn(a.x, a.y);
        H.h[1] = __floats2half2_rn(a.z, a.w);
        H.h[2] = __floats2half2_rn(b.x, b.y);
        H.h[3] = __floats2half2_rn(b.z, b.w);
        hd[i] = H.u;
    }
    nrm[idx] = s;
}

// -------- main fused mma.sync kernel: persistent X tile, loop over 4 Y tiles --------
// Grid (MM/(128*MT), NN/128, BB) = (8, 32, 8). 256 threads = 8 warps, 4(m) x 2(n).
// Trick: acc initialized to -(x2+y2)/2, so post-MMA acc = -sq/2 and min-sq == max-acc.
#define TB (TILE * 128)                    // 16384 B per fp16 tile
#define OFF_XT   0
#define OFF_YT0  (OFF_XT + TB)
#define OFF_YT1  (OFF_YT0 + TB)
#define OFF_X2   (OFF_YT1 + TB)
#define OFF_Y20  (OFF_X2 + 512)
#define OFF_Y21  (OFF_Y20 + 512)
#define OFF_CMIN (OFF_Y21 + 512)
#define SMEM_TOTAL (OFF_CMIN + 512)        // 51200 B

__global__ __launch_bounds__(256, 2)
void chamfer_mma_kernel() {
    extern __shared__ char smem[];
    uint32_t sb = smem_to_u32(smem);
    const int tid = threadIdx.x;
    const int wid = tid >> 5;
    const int lid = tid & 31;
    const int wr  = wid >> 1;     // m block of 32
    const int wc  = wid & 1;      // n block of 64
    const int b   = blockIdx.z;
    const int n0  = blockIdx.y * TILE;
    const int m0b = blockIdx.x * (TILE * MT);

    float*    x2s    = reinterpret_cast<float*>(smem + OFF_X2);
    unsigned* s_cmin = reinterpret_cast<unsigned*>(smem + OFF_CMIN);
    float*    y2sbuf[2] = {reinterpret_cast<float*>(smem + OFF_Y20),
                           reinterpret_cast<float*>(smem + OFF_Y21)};
    const uint32_t ytb[2] = {sb + OFF_YT0, sb + OFF_YT1};

    // thread's fill mapping (4 uint4 per tile)
    const int fr0 = tid >> 3;              // rows tid/8 + {0,32,64,96}
    const int fq  = tid & 7;
    uint32_t fdst[4];
    size_t   fsrc[4];
#pragma unroll
    for (int it = 0; it < 4; ++it) {
        int r = fr0 + it * 32;
        fdst[it] = SWZ128((uint32_t)(r * 128 + fq * 16));
        fsrc[it] = (size_t)r * 8 + fq;
    }

    // prologue: group0 = {X, Y0}, group1 = {Y1}
    const uint4* sx = g_xh4 + (size_t)(b * NN + n0) * 8;
    const uint4* sy = g_yh4 + (size_t)(b * MM + m0b) * 8;
#pragma unroll
    for (int it = 0; it < 4; ++it) cp_async16(sb + OFF_XT + fdst[it], sx + fsrc[it]);
#pragma unroll
    for (int it = 0; it < 4; ++it) cp_async16(ytb[0] + fdst[it], sy + fsrc[it]);
    CP_COMMIT();
#pragma unroll
    for (int it = 0; it < 4; ++it) cp_async16(ytb[1] + fdst[it], sy + 1024 + fsrc[it]);
    CP_COMMIT();

    if (tid < 128) { x2s[tid] = g_x2[b * NN + n0 + tid]; s_cmin[tid] = 0x7f800000u; }
    else {
        int j = tid - 128;
        y2sbuf[0][j] = g_y2[b * MM + m0b + j];
        y2sbuf[1][j] = g_y2[b * MM + m0b + 128 + j];
    }

    // row maxima of acc (= -sq/2), accumulated across all m-tiles
    float rowM[2][2];
#pragma unroll
    for (int mt = 0; mt < 2; ++mt)
#pragma unroll
        for (int h = 0; h < 2; ++h) rowM[mt][h] = -__int_as_float(0x7f800000);

    float xh[2][2];   // -0.5 * x2 per owned row; loaded after first sync

#pragma unroll
    for (int t = 0; t < MT; ++t) {
        if (t < MT - 1) { CP_WAIT(1); } else { CP_WAIT(0); }
        __syncthreads();
        if (t == 0) {
#pragma unroll
            for (int mt = 0; mt < 2; ++mt)
#pragma unroll
                for (int h = 0; h < 2; ++h)
                    xh[mt][h] = -0.5f * x2s[wr * 32 + mt * 16 + (lid >> 2) + 8 * h];
        }

        const uint32_t Yb = ytb[t & 1];
        const float* y2s  = y2sbuf[t & 1];

        // -0.5 * y2 per owned col
        float yh[8][2];
#pragma unroll
        for (int nt = 0; nt < 8; ++nt)
#pragma unroll
            for (int p = 0; p < 2; ++p)
                yh[nt][p] = -0.5f * y2s[wc * 64 + nt * 8 + (lid & 3) * 2 + p];

        float acc[2][8][4];
#pragma unroll
        for (int mt = 0; mt < 2; ++mt)
#pragma unroll
            for (int nt = 0; nt < 8; ++nt)
#pragma unroll
                for (int c = 0; c < 4; ++c)
                    acc[mt][nt][c] = xh[mt][c >> 1] + yh[nt][c & 1];

#pragma unroll
        for (int ks = 0; ks < 4; ++ks) {
            uint32_t a[2][4];
#pragma unroll
            for (int mt = 0; mt < 2; ++mt) {
                int row  = wr * 32 + mt * 16 + (lid & 15);
                int colb = ks * 32 + (lid >> 4) * 16;
                uint32_t off = (uint32_t)(row * 128 + (colb ^ ((row & 7) * 16)));
                ldsm_x4(a[mt], sb + OFF_XT + off);
            }
            uint32_t bf[4][4];
#pragma unroll
            for (int j2 = 0; j2 < 4; ++j2) {
                int row  = wc * 64 + j2 * 16 + (lid & 7) + ((lid >> 4) & 1) * 8;
                int colb = ks * 32 + ((lid >> 3) & 1) * 16;
                uint32_t off = (uint32_t)(row * 128 + (colb ^ ((row & 7) * 16)));
                ldsm_x4(bf[j2], Yb + off);
            }
#pragma unroll
            for (int mt = 0; mt < 2; ++mt)
#pragma unroll
                for (int nt = 0; nt < 8; ++nt)
                    mma16816(acc[mt][nt], a[mt], &bf[nt >> 1][(nt & 1) * 2]);
        }

        // epilogue: track max acc per row / per col (2 FMNMX per acc)
        float colM[8][2];
#pragma unroll
        for (int nt = 0; nt < 8; ++nt)
#pragma unroll
            for (int p = 0; p < 2; ++p) colM[nt][p] = -__int_as_float(0x7f800000);

#pragma unroll
        for (int mt = 0; mt < 2; ++mt)
#pragma unroll
            for (int nt = 0; nt < 8; ++nt)
#pragma unroll
                for (int c = 0; c < 4; ++c) {
                    float v = acc[mt][nt][c];
                    rowM[mt][c >> 1] = fmaxf(rowM[mt][c >> 1], v);
                    colM[nt][c & 1]  = fmaxf(colM[nt][c & 1], v);
                }

        // col maxima -> smem min-sq (lanes sharing a col differ in lid bits 2-4)
        const int m0 = m0b + t * TILE;
#pragma unroll
        for (int nt = 0; nt < 8; ++nt)
#pragma unroll
            for (int p = 0; p < 2; ++p) {
                float v = colM[nt][p];
                v = fmaxf(v, __shfl_xor_sync(0xffffffffu, v, 4));
                v = fmaxf(v, __shfl_xor_sync(0xffffffffu, v, 8));
                v = fmaxf(v, __shfl_xor_sync(0xffffffffu, v, 16));
                if (lid < 4) {
                    float sq = fmaxf(-2.f * v, 0.f);
                    atomicMin(&s_cmin[wc * 64 + nt * 8 + (lid & 3) * 2 + p],
                              __float_as_uint(sq));
                }
            }
        __syncthreads();

        // flush col mins, reset, and prefetch Y_{t+2}
        if (tid < 128) {
            atomicMin(&g_cmin[b * MM + m0 + tid], s_cmin[tid]);
            s_cmin[tid] = 0x7f800000u;
        }
        if (t < MT - 2) {
#pragma unroll
            for (int it = 0; it < 4; ++it)
                cp_async16(ytb[t & 1] + fdst[it], sy + (size_t)(t + 2) * 1024 + fsrc[it]);
            CP_COMMIT();
            if (tid >= 128) {
                int j = tid - 128;
                y2sbuf[t & 1][j] = g_y2[b * MM + m0b + (t + 2) * 128 + j];
            }
        }
    }

    // row maxima accumulated over all m-tiles; flush once (lid bits 0-1 share a row)
#pragma unroll
    for (int mt = 0; mt < 2; ++mt)
#pragma unroll
        for (int h = 0; h < 2; ++h) {
            float v = rowM[mt][h];
            v = fmaxf(v, __shfl_xor_sync(0xffffffffu, v, 1));
            v = fmaxf(v, __shfl_xor_sync(0xffffffffu, v, 2));
            if ((lid & 3) == 0) {
                float sq = fmaxf(-2.f * v, 0.f);
                atomicMin(&g_rmin[b * NN + n0 + wr * 32 + mt * 16 + (lid >> 2) + 8 * h],
                          __float_as_uint(sq));
            }
        }
}

// -------- partial reduce: sqrt of min-sq, scaled --------
__global__ void chamfer_partial_kernel() {
    __shared__ float red[256];
    const int tid = threadIdx.x;
    const int t = blockIdx.x * 256 + tid;     // 0..65535
    float sq;
    if (t < ROWS_X) sq = __uint_as_float(g_rmin[t]);
    else            sq = __uint_as_float(g_cmin[t - ROWS_X]);
    red[tid] = sqrtf(sq) * (1.f / (float)ROWS_X);   // both sides divide by 32768
    __syncthreads();
    for (int o = 128; o > 0; o >>= 1) {
        if (tid < o) red[tid] += red[tid + o];
        __syncthreads();
    }
    if (tid == 0) g_part[blockIdx.x] = red[0];
}

__global__ void chamfer_final_kernel(float* __restrict__ out) {
    __shared__ float red[256];
    int tid = threadIdx.x;
    red[tid] = g_part[tid];
    __syncthreads();
    for (int o = 128; o > 0; o >>= 1) {
        if (tid < o) red[tid] += red[tid + o];
        __syncthreads();
    }
    if (tid == 0) out[0] = red[0];
}

extern "C" void kernel_launch(void* const* d_in, const int* in_sizes, int n_in,
                              void* d_out, int out_size) {
    const float* X = (const float*)d_in[0];  // [B, N, K]
    const float* Y = (const float*)d_in[1];  // [B, M, K]
    float* out = (float*)d_out;

    cudaFuncSetAttribute(chamfer_mma_kernel,
                         cudaFuncAttributeMaxDynamicSharedMemorySize, SMEM_TOTAL);

    chamfer_convert_kernel<<<(ROWS_X + ROWS_Y) / 256, 256>>>(X, Y);
    dim3 grid(MM / (TILE * MT), NN / TILE, BB);
    chamfer_mma_kernel<<<grid, 256, SMEM_TOTAL>>>();
    chamfer_partial_kernel<<<256, 256>>>();
    chamfer_final_kernel<<<1, 256>>>(out);
}